// round 2
// baseline (speedup 1.0000x reference)
#include <cuda_runtime.h>

#define PSZ 16
#define HW 224
#define NP 14          // patches per spatial dim (224/16)
#define SSTRIDE 225    // smem row stride in floats (odd -> conflict-free transposed reads)
#define CHUNKS 896     // 16*224/4 float4 chunks per strip

// Flag: 1 if mask buffer is int32 (one int per bool), 0 if it is uint8.
__device__ int g_mask_is_int32;

__global__ void detect_mask_dtype_kernel(const unsigned int* __restrict__ mw)
{
    // Scan the first 1024 words (4 KB, safely within both possible buffer sizes:
    // uint8 mask = 50176 B, int32 mask = 200704 B).
    // int32 bool array: every word is 0 or 1.
    // uint8 bool array: a word packs 4 random 0/1 bytes -> word > 1 with p=7/8.
    int t = threadIdx.x;
    int bad = 0;
    #pragma unroll
    for (int i = 0; i < 4; i++) {
        unsigned v = mw[t + i * 256];
        bad |= (v > 1u);
    }
    bad = __syncthreads_or(bad);
    if (t == 0) g_mask_is_int32 = bad ? 0 : 1;
}

__global__ __launch_bounds__(256) void patch_rotate_kernel(
    const float* __restrict__ x,
    const void* __restrict__ mask_raw,
    float* __restrict__ out)
{
    __shared__ float tile[PSZ * SSTRIDE];   // 16 x 225 floats = 14.4 KB
    __shared__ unsigned char m[NP];

    const int bid = blockIdx.x;
    const int hi  = bid % NP;          // patch-row index
    const int bc  = bid / NP;          // b*3 + c
    const int b   = bc / 3;

    const int t = threadIdx.x;
    if (t < NP) {
        int midx = b * (NP * NP) + t * NP + hi;   // mask[b, wi=t, hi]
        if (g_mask_is_int32)
            m[t] = (((const int*)mask_raw)[midx] != 0);
        else
            m[t] = (((const unsigned char*)mask_raw)[midx] != 0);
    }

    const float* src = x   + (size_t)bc * (HW * HW) + (size_t)hi * (PSZ * HW);
    float*       dst = out + (size_t)bc * (HW * HW) + (size_t)hi * (PSZ * HW);

    const int rot = (t >> 3) & 3;   // per-thread element rotation -> conflict-free scalar STS/LDS

    // ---- Load phase: 3584 contiguous floats (coalesced float4), stage into padded smem ----
    #pragma unroll
    for (int j = 0; j < 4; j++) {
        int q = t + j * 256;
        if (q < CHUNKS) {
            float4 v = reinterpret_cast<const float4*>(src)[q];
            int r = q / 56;            // row within strip (0..15)
            int c = (q % 56) * 4;      // col within strip (0..220, step 4)
            float vv[4] = {v.x, v.y, v.z, v.w};
            #pragma unroll
            for (int i = 0; i < 4; i++) {
                int e = (i + rot) & 3;
                tile[r * SSTRIDE + c + e] = vv[e];
            }
        }
    }
    __syncthreads();

    // ---- Write phase: gather (straight or per-patch transposed), coalesced float4 stores ----
    #pragma unroll
    for (int j = 0; j < 4; j++) {
        int q = t + j * 256;
        if (q < CHUNKS) {
            int a   = q / 56;          // output row within strip (p1 index i)
            int col = (q % 56) * 4;    // output col base
            int wi  = col >> 4;        // patch column index
            int p0  = col & 15;        // p2 base within patch (j index)

            // branchless address select: avoids warp divergence on mixed-mask warps
            bool mm = (m[wi] != 0);
            int base_m = p0 * SSTRIDE + wi * PSZ + a;  // transposed: tile[j][wi*16 + i]
            int base_u = a * SSTRIDE + col;            // straight:   tile[i][col + j]

            float vv[4];
            #pragma unroll
            for (int i = 0; i < 4; i++) {
                int e = (i + rot) & 3;
                int addr = mm ? (base_m + e * SSTRIDE) : (base_u + e);
                vv[e] = tile[addr];
            }
            reinterpret_cast<float4*>(dst)[q] = make_float4(vv[0], vv[1], vv[2], vv[3]);
        }
    }
}

extern "C" void kernel_launch(void* const* d_in, const int* in_sizes, int n_in,
                              void* d_out, int out_size)
{
    const float* x    = (const float*)d_in[0];
    const void*  mask = d_in[1];
    float*       out  = (float*)d_out;

    detect_mask_dtype_kernel<<<1, 256>>>((const unsigned int*)mask);
    // grid: one block per (b, c, patch-row) strip = 256*3*14 = 10752 blocks
    patch_rotate_kernel<<<10752, 256>>>(x, mask, out);
}

// round 3
// speedup vs baseline: 1.2071x; 1.2071x over previous
#include <cuda_runtime.h>

#define PSZ 16
#define HW 224
#define NP 14          // patches per spatial dim (224/16)
#define SSTRIDE 225    // smem row stride in floats (225 mod 32 == 1 -> conflict-free)

__global__ __launch_bounds__(224) void patch_rotate_kernel(
    const float* __restrict__ x,
    const void* __restrict__ mask_raw,
    float* __restrict__ out)
{
    __shared__ float tile[PSZ * SSTRIDE];   // 16 x 225 floats = 14.4 KB
    __shared__ unsigned char m[NP];

    const int bid = blockIdx.x;
    const int hi  = bid % NP;          // patch-row index
    const int bc  = bid / NP;          // b*3 + c
    const int b   = bc / 3;
    const int t   = threadIdx.x;       // 0..223

    // ---- dtype probe: read 64 words of the mask buffer (256 B, L2-broadcast) ----
    // int32 bool array: every word is 0 or 1.  uint8 bool array: word > 1 w.p. 7/8
    // per word -> P(miss over 64 words) = 8^-64.
    unsigned dv = 0;
    if (t < 64) dv = ((const unsigned int*)mask_raw)[t];

    const float* src = x   + (size_t)bc * (HW * HW) + (size_t)hi * (PSZ * HW);
    float*       dst = out + (size_t)bc * (HW * HW) + (size_t)hi * (PSZ * HW);

    // hoisted geometry: q = t + 224*j, 224 = 4*56  =>  row = t/56 + 4j, colchunk = t%56
    const int tr  = t / 56;            // 0..3   (computed once)
    const int tc  = t % 56;            // 0..55  (computed once)
    const int rot = (t >> 3) & 3;      // per-thread element rotation (bank-conflict breaker)

    // ---- load phase: 4 coalesced float4 per thread, kept in registers ----
    float4 v[4];
    #pragma unroll
    for (int j = 0; j < 4; j++)
        v[j] = reinterpret_cast<const float4*>(src)[t + 224 * j];

    const int is_int32 = !__syncthreads_or(t < 64 ? (dv > 1u) : 0);

    if (t < NP) {
        int midx = b * (NP * NP) + t * NP + hi;   // mask[b, wi=t, hi]
        unsigned char mv;
        if (is_int32) mv = (((const int*)mask_raw)[midx] != 0);
        else          mv = (((const unsigned char*)mask_raw)[midx] != 0);
        m[t] = mv;
    }

    // ---- stage to smem (rotated scalar STS, conflict-free) ----
    #pragma unroll
    for (int j = 0; j < 4; j++) {
        int base = (tr + 4 * j) * SSTRIDE + tc * 4;
        float vv[4] = {v[j].x, v[j].y, v[j].z, v[j].w};
        #pragma unroll
        for (int i = 0; i < 4; i++) {
            int e = (i + rot) & 3;
            tile[base + e] = vv[e];
        }
    }
    __syncthreads();

    // ---- write phase ----
    const int wi = tc >> 2;            // patch column index (constant per thread)
    const int p0 = (tc & 3) * 4;       // p2 base within patch (constant per thread)
    const bool mm = (m[wi] != 0);
    const int gbase = p0 * SSTRIDE + wi * PSZ + tr;  // transposed-gather base

    #pragma unroll
    for (int j = 0; j < 4; j++) {
        float4 o;
        if (mm) {
            // per-patch transpose: out[a][col+e] = tile[p0+e][wi*16 + a], a = tr + 4j
            float vv[4];
            #pragma unroll
            for (int i = 0; i < 4; i++) {
                int e = (i + rot) & 3;
                vv[e] = tile[gbase + 4 * j + e * SSTRIDE];
            }
            o = make_float4(vv[0], vv[1], vv[2], vv[3]);
        } else {
            o = v[j];   // unmasked: direct register passthrough, no smem read
        }
        reinterpret_cast<float4*>(dst)[t + 224 * j] = o;
    }
}

extern "C" void kernel_launch(void* const* d_in, const int* in_sizes, int n_in,
                              void* d_out, int out_size)
{
    const float* x    = (const float*)d_in[0];
    const void*  mask = d_in[1];
    float*       out  = (float*)d_out;

    // one block per (b, c, patch-row) strip = 256*3*14 = 10752 blocks
    patch_rotate_kernel<<<10752, 224>>>(x, mask, out);
}